// round 12
// baseline (speedup 1.0000x reference)
#include <cuda_runtime.h>
#include <cuda_bf16.h>

// ht[b,d] = sum_{s=start}^{start+x-1} hidden[b,s,d]
// start = sum(mask[B-1, :]) - x   (JAX x64-disabled: mask & x are int32)
//
// Fast path (one barrier, max occupancy): 256 blocks x 1024 threads =
// 32 float4-cols x 32 s-groups. Per thread: 2 speculative window loads
// (rows [S-64,S), load-independent addresses), ONE 8-byte mask word
// compared against 0x0000000100000001 (1024 threads cover the whole row),
// partials staged in smem BEFORE the single __syncthreads_and, epilogue by
// warp 0 with conflict-free lane=col LDS (32-deep, pipelined).
// Slow path: generic (any mask / any x), block-uniform branch.

__global__ void __launch_bounds__(1024)
srsmlp_window_sum_kernel(const float* __restrict__ hidden,
                         const int* __restrict__ mask,
                         const int* __restrict__ xptr,
                         float* __restrict__ out,
                         int B, int S, int D4, int chunks /* D4/32 */)
{
    const int tid = threadIdx.x;
    const int col = tid & 31;         // float4 column within 32-wide chunk
    const int sg  = tid >> 5;         // s-group 0..31 (== warp id)
    const int b     = blockIdx.x / chunks;
    const int chunk = blockIdx.x - b * chunks;

    const int d4 = (chunk << 5) + col;
    const unsigned rowB = (unsigned)(D4 << 4);        // row stride in bytes

    const int x = __ldg(xptr);        // tiny scalar, on the wire first

    // ---- speculative window loads: rows [max(S-64,0), ...), no deps ----
    const bool can_spec = (S >= 64);
    const int  gs = can_spec ? (S - 64) : 0;
    const char* sbase = (const char*)hidden
        + ((long long)b * S + gs) * rowB + ((unsigned)d4 << 4);

    float4 v0 = *(const float4*)(sbase + (unsigned)(sg)      * rowB);
    float4 v1 = *(const float4*)(sbase + (unsigned)(sg + 32) * rowB);

    // ---- mask predicate: ONE 8B load per thread ----
    const int* mrow = mask + (long long)(B - 1) * S;
    const int  S2   = S >> 1;                       // 8B words
    const unsigned long long* m1 =
        reinterpret_cast<const unsigned long long*>(mrow);
    const unsigned long long ONES = 0x0000000100000001ULL;

    int okbits = (x == 64) & (int)can_spec & (int)((S & 1) == 0);
    if (S2 == 1024) {                 // common case: exactly 1 load/thread
        okbits &= (m1[tid] == ONES);
    } else if ((S & 1) == 0) {
        for (int i = tid; i < S2; i += 1024)
            okbits &= (m1[i] == ONES);
    }

    // ---- combine the two speculative partials, stage in smem ----
    float4 a;
    a.x = v0.x + v1.x;
    a.y = v0.y + v1.y;
    a.z = v0.z + v1.z;
    a.w = v0.w + v1.w;

    __shared__ float4 red[32][32];    // 16 KB: 32 s-group partials x 32 cols
    red[sg][col] = a;

    // ---- single barrier: sync + block-wide AND of predicate ----
    const int allok = __syncthreads_and(okbits);

    float4* __restrict__ out4 = reinterpret_cast<float4*>(out);

    if (allok) {
        if (tid < 32) {               // warp 0; lane=col -> conflict-free LDS
            float4 t0 = red[0][tid];
            float4 t1 = red[1][tid];
            float4 t2 = red[2][tid];
            float4 t3 = red[3][tid];
            #pragma unroll
            for (int j = 4; j < 32; j += 4) {
                float4 w0 = red[j+0][tid];
                float4 w1 = red[j+1][tid];
                float4 w2 = red[j+2][tid];
                float4 w3 = red[j+3][tid];
                t0.x += w0.x; t0.y += w0.y; t0.z += w0.z; t0.w += w0.w;
                t1.x += w1.x; t1.y += w1.y; t1.z += w1.z; t1.w += w1.w;
                t2.x += w2.x; t2.y += w2.y; t2.z += w2.z; t2.w += w2.w;
                t3.x += w3.x; t3.y += w3.y; t3.z += w3.z; t3.w += w3.w;
            }
            float4 t;
            t.x = (t0.x + t1.x) + (t2.x + t3.x);
            t.y = (t0.y + t1.y) + (t2.y + t3.y);
            t.z = (t0.z + t1.z) + (t2.z + t3.z);
            t.w = (t0.w + t1.w) + (t2.w + t3.w);
            out4[(long long)b * D4 + (chunk << 5) + tid] = t;
        }
        return;
    }

    // ================= slow path (any mask / any x; block-uniform) =========
    __shared__ int s_len;
    if (tid == 0) s_len = 0;
    __syncthreads();
    {
        const int S4 = S >> 2;
        int macc = 0;
        for (int i = tid; i < S4; i += 1024) {
            int4 m = reinterpret_cast<const int4*>(mrow)[i];
            macc += m.x + m.y + m.z + m.w;
        }
        for (int i = (S4 << 2) + tid; i < S; i += 1024)
            macc += mrow[i];
        #pragma unroll
        for (int off = 16; off > 0; off >>= 1)
            macc += __shfl_down_sync(0xFFFFFFFFu, macc, off);
        if ((tid & 31) == 0)
            atomicAdd(&s_len, macc);
    }
    __syncthreads();

    const int start = s_len - x;
    float4 acc = make_float4(0.f,0.f,0.f,0.f);
    const char* tbase = (const char*)hidden
        + ((long long)b * S + start) * rowB + ((unsigned)d4 << 4);
    for (int r = sg; r < x; r += 32) {
        float4 v = *(const float4*)(tbase + (unsigned)r * rowB);
        acc.x += v.x; acc.y += v.y; acc.z += v.z; acc.w += v.w;
    }

    __syncthreads();                  // red[] reuse
    red[sg][col] = acc;
    __syncthreads();

    if (tid < 32) {
        float4 t = red[0][tid];
        #pragma unroll
        for (int j = 1; j < 32; ++j) {
            float4 v = red[j][tid];
            t.x += v.x; t.y += v.y; t.z += v.z; t.w += v.w;
        }
        out4[(long long)b * D4 + (chunk << 5) + tid] = t;
    }
}

extern "C" void kernel_launch(void* const* d_in, const int* in_sizes, int n_in,
                              void* d_out, int out_size)
{
    const float* hidden = (const float*)d_in[0];
    const int*   mask   = (const int*)d_in[1];
    const int*   xptr   = (const int*)d_in[2];
    float*       out    = (float*)d_out;

    const long long hidden_elems = in_sizes[0];
    const long long mask_elems   = in_sizes[1];

    const int D  = (int)(hidden_elems / mask_elems);  // 1024
    const int B  = out_size / D;                      // 32
    const int S  = (int)(mask_elems / B);             // 2048
    const int D4 = D >> 2;                            // 256
    const int chunks = D4 >> 5;                       // 8 (32 float4-cols/block)

    dim3 grid(B * chunks);                            // 256 blocks
    srsmlp_window_sum_kernel<<<grid, 1024>>>(hidden, mask, xptr, out,
                                             B, S, D4, chunks);
}